// round 15
// baseline (speedup 1.0000x reference)
#include <cuda_runtime.h>
#include <cuda_fp16.h>
#include <cstdint>

#define M_DIM 8192
#define N_DIM 4096
#define K_DIM 4096
#define RANK_K 15099493u   // floor(0.9f * 16777215.0f) in fp32 semantics, frac == 0

// ---------------- device scratch (static globals: allowed) ----------------
__device__ __half   g_X16[(size_t)M_DIM * K_DIM];   // 64 MB
__device__ __half   g_W16[(size_t)N_DIM * K_DIM];   // 32 MB
__device__ unsigned g_hist1[8192];
__device__ unsigned g_hist2[262144];
__device__ unsigned g_selP;
__device__ unsigned g_selBase;
__device__ float    g_thresh;

// ---------------- PTX helpers (base ISA only) ----------------
__device__ __forceinline__ uint32_t smem_u32(const void* p) {
    uint32_t a;
    asm("{ .reg .u64 t; cvta.to.shared.u64 t, %1; cvt.u32.u64 %0, t; }" : "=r"(a) : "l"(p));
    return a;
}
__device__ __forceinline__ void cp16(uint32_t s, const void* g) {
    asm volatile("cp.async.cg.shared.global [%0], [%1], 16;" :: "r"(s), "l"(g));
}
__device__ __forceinline__ void cp_commit() { asm volatile("cp.async.commit_group;" ::: "memory"); }
__device__ __forceinline__ void cp_wait1()  { asm volatile("cp.async.wait_group 1;" ::: "memory"); }

__device__ __forceinline__ void ldsm4(uint32_t& r0, uint32_t& r1, uint32_t& r2, uint32_t& r3,
                                      uint32_t addr) {
    asm volatile("ldmatrix.sync.aligned.m8n8.x4.shared.b16 {%0,%1,%2,%3}, [%4];"
                 : "=r"(r0), "=r"(r1), "=r"(r2), "=r"(r3) : "r"(addr));
}

__device__ __forceinline__ void mma16816(float* c, const uint32_t* a, uint32_t b0, uint32_t b1) {
    asm volatile(
        "mma.sync.aligned.m16n8k16.row.col.f32.f16.f16.f32 "
        "{%0,%1,%2,%3}, {%4,%5,%6,%7}, {%8,%9}, {%0,%1,%2,%3};"
        : "+f"(c[0]), "+f"(c[1]), "+f"(c[2]), "+f"(c[3])
        : "r"(a[0]), "r"(a[1]), "r"(a[2]), "r"(a[3]), "r"(b0), "r"(b1));
}

// ---------------- selection: exact order statistic of |w| bits ----------------
__global__ void zero_kernel() {
    int i = blockIdx.x * blockDim.x + threadIdx.x;
    int st = gridDim.x * blockDim.x;
    for (int j = i; j < 8192; j += st) g_hist1[j] = 0;
    for (int j = i; j < 262144; j += st) g_hist2[j] = 0;
}

__global__ void hist1_kernel(const float4* __restrict__ w, int n4) {
    __shared__ unsigned sh[8192];
    for (int i = threadIdx.x; i < 8192; i += blockDim.x) sh[i] = 0;
    __syncthreads();
    int idx = blockIdx.x * blockDim.x + threadIdx.x;
    int stride = gridDim.x * blockDim.x;
    for (int i = idx; i < n4; i += stride) {
        float4 v = w[i];
        atomicAdd(&sh[(__float_as_uint(v.x) & 0x7FFFFFFFu) >> 18], 1u);
        atomicAdd(&sh[(__float_as_uint(v.y) & 0x7FFFFFFFu) >> 18], 1u);
        atomicAdd(&sh[(__float_as_uint(v.z) & 0x7FFFFFFFu) >> 18], 1u);
        atomicAdd(&sh[(__float_as_uint(v.w) & 0x7FFFFFFFu) >> 18], 1u);
    }
    __syncthreads();
    for (int i = threadIdx.x; i < 8192; i += blockDim.x) {
        unsigned c = sh[i];
        if (c) atomicAdd(&g_hist1[i], c);
    }
}

__global__ void scan1_kernel(unsigned rank) {
    __shared__ unsigned partial[1024];
    int t = threadIdx.x;
    unsigned v[8];
    unsigned s = 0;
#pragma unroll
    for (int i = 0; i < 8; i++) { v[i] = g_hist1[t * 8 + i]; s += v[i]; }
    partial[t] = s;
    __syncthreads();
    for (int ofs = 1; ofs < 1024; ofs <<= 1) {
        unsigned x = (t >= ofs) ? partial[t - ofs] : 0u;
        __syncthreads();
        partial[t] += x;
        __syncthreads();
    }
    unsigned base = partial[t] - s;  // exclusive prefix
    if (rank >= base && rank < partial[t]) {
        unsigned cum = base;
#pragma unroll
        for (int i = 0; i < 8; i++) {
            if (rank < cum + v[i]) { g_selP = (unsigned)(t * 8 + i); g_selBase = cum; break; }
            cum += v[i];
        }
    }
}

// hist2 (W) fused with conv_x (X) -- independent workloads, concurrent DRAM streams
#define XBLK 1184
#define HBLK 592
__global__ void hist2_convx_kernel(const float4* __restrict__ x, const float4* __restrict__ w) {
    if (blockIdx.x < XBLK) {
        int idx = blockIdx.x * blockDim.x + threadIdx.x;
        int stride = XBLK * blockDim.x;
        uint2* out = reinterpret_cast<uint2*>(g_X16);
        const int n4 = (M_DIM * K_DIM) / 4;
        for (int i = idx; i < n4; i += stride) {
            float4 v = x[i];
            __half2 h0 = __floats2half2_rn(v.x, v.y);
            __half2 h1 = __floats2half2_rn(v.z, v.w);
            uint2 o;
            o.x = *reinterpret_cast<unsigned*>(&h0);
            o.y = *reinterpret_cast<unsigned*>(&h1);
            out[i] = o;
        }
    } else {
        unsigned P = g_selP;
        int idx = (blockIdx.x - XBLK) * blockDim.x + threadIdx.x;
        int stride = HBLK * blockDim.x;
        const int n4 = (N_DIM * K_DIM) / 4;
        for (int i = idx; i < n4; i += stride) {
            float4 v = w[i];
            unsigned b;
            b = __float_as_uint(v.x) & 0x7FFFFFFFu; if ((b >> 18) == P) atomicAdd(&g_hist2[b & 0x3FFFFu], 1u);
            b = __float_as_uint(v.y) & 0x7FFFFFFFu; if ((b >> 18) == P) atomicAdd(&g_hist2[b & 0x3FFFFu], 1u);
            b = __float_as_uint(v.z) & 0x7FFFFFFFu; if ((b >> 18) == P) atomicAdd(&g_hist2[b & 0x3FFFFu], 1u);
            b = __float_as_uint(v.w) & 0x7FFFFFFFu; if ((b >> 18) == P) atomicAdd(&g_hist2[b & 0x3FFFFu], 1u);
        }
    }
}

__global__ void scan2_kernel(unsigned rank) {
    __shared__ unsigned partial[1024];
    int t = threadIdx.x;
    unsigned s = 0;
    for (int i = 0; i < 256; i++) s += g_hist2[t * 256 + i];
    partial[t] = s;
    __syncthreads();
    for (int ofs = 1; ofs < 1024; ofs <<= 1) {
        unsigned x = (t >= ofs) ? partial[t - ofs] : 0u;
        __syncthreads();
        partial[t] += x;
        __syncthreads();
    }
    unsigned base = partial[t] - s;
    unsigned rl = rank - g_selBase;
    if (rl >= base && rl < partial[t]) {
        unsigned cum = base;
        for (int i = 0; i < 256; i++) {
            unsigned c = g_hist2[t * 256 + i];
            if (rl < cum + c) {
                g_thresh = __uint_as_float((g_selP << 18) | (unsigned)(t * 256 + i));
                break;
            }
            cum += c;
        }
    }
}

__global__ void conv_w_kernel(const float4* __restrict__ w, int n4) {
    float t = g_thresh;
    int idx = blockIdx.x * blockDim.x + threadIdx.x;
    int stride = gridDim.x * blockDim.x;
    uint2* out = reinterpret_cast<uint2*>(g_W16);
    for (int i = idx; i < n4; i += stride) {
        float4 v = w[i];
        float a0 = (fabsf(v.x) >= t) ? v.x : 0.0f;
        float a1 = (fabsf(v.y) >= t) ? v.y : 0.0f;
        float a2 = (fabsf(v.z) >= t) ? v.z : 0.0f;
        float a3 = (fabsf(v.w) >= t) ? v.w : 0.0f;
        __half2 h0 = __floats2half2_rn(a0, a1);
        __half2 h1 = __floats2half2_rn(a2, a3);
        uint2 o;
        o.x = *reinterpret_cast<unsigned*>(&h0);
        o.y = *reinterpret_cast<unsigned*>(&h1);
        out[i] = o;
    }
}

// ---- Hybrid GEMM: 128x128 CTA, 12 warps, occ 1.
// ----   warps 0-7: mma.sync on cols [0,104)  (warp tile 16m x 104n)
// ----   warps 8-11: HFMA2 (fma pipe) on cols [104,128), fp32 promote every 32 K
#define BM 128
#define BN 128
#define BKH 64                      // K halves per stage (128 B rows -> SW128)
#define NK (K_DIM / BKH)            // 64
#define STG 3
#define OP_BYTES (BM * 128)         // 16384
#define STAGE_B (2 * OP_BYTES)      // 32768
#define SMEM_GEMM (STG * STAGE_B)   // 98304
#define NTHR 384

__device__ __forceinline__ void load_stage(uint32_t st, int m0, int n0, int kidx, int tid) {
    const __half* Xp = g_X16 + (size_t)m0 * K_DIM + (size_t)kidx * BKH;
    const __half* Wp = g_W16 + (size_t)n0 * K_DIM + (size_t)kidx * BKH;
#pragma unroll
    for (int i = 0; i < 6; i++) {
        int c = tid + i * NTHR;          // 0..2303; valid < 2048
        if (c < 1024) {                  // A: 128 rows x 8 chunks
            int row = c >> 3, ci = c & 7;
            cp16(st + row * 128 + ((ci ^ (row & 7)) << 4), Xp + (size_t)row * K_DIM + ci * 8);
        } else if (c < 2048) {           // B: 128 rows x 8 chunks
            int c2 = c - 1024;
            int row = c2 >> 3, ci = c2 & 7;
            cp16(st + OP_BYTES + row * 128 + ((ci ^ (row & 7)) << 4), Wp + (size_t)row * K_DIM + ci * 8);
        }
    }
}

__global__ void __launch_bounds__(NTHR, 1) gemm_kernel(const float* __restrict__ bias,
                                                       float* __restrict__ out) {
    extern __shared__ char smraw[];
    const uint32_t sbase = smem_u32(smraw);
    const int tid = threadIdx.x;
    const int wid = tid >> 5;
    const int lane = tid & 31;
    const int m0 = blockIdx.y * BM;
    const int n0 = blockIdx.x * BN;

    // mma lane geometry
    const int g   = lane >> 3;
    const int lr  = lane & 7;
    const int r16 = ((g & 1) << 3) + lr;
    const int kg  = g >> 1;

    // ffma thread geometry (warps 8-11)
    const int ft  = tid - 256;            // 0..127 for ffma role
    const int fm  = (ft & 31) * 4;        // 4 local m rows
    const int fnl = (ft >> 5) * 6;        // 0,6,12,18
    const int fn  = 104 + fnl;            // W row / out col base

    float acc[13][4];                     // mma accumulators (warp tile 16 x 104)
    __half2 acch[4][6];                   // ffma half2 (k-paired) accumulators
    float   accf[4][6];                   // ffma fp32 accumulators
#pragma unroll
    for (int t = 0; t < 13; t++)
#pragma unroll
        for (int k = 0; k < 4; k++) acc[t][k] = 0.0f;
#pragma unroll
    for (int i = 0; i < 4; i++)
#pragma unroll
        for (int j = 0; j < 6; j++) { acch[i][j] = __float2half2_rn(0.0f); accf[i][j] = 0.0f; }

    // prologue: stages 0,1 in flight
    load_stage(sbase + 0 * STAGE_B, m0, n0, 0, tid); cp_commit();
    load_stage(sbase + 1 * STAGE_B, m0, n0, 1, tid); cp_commit();

    for (int ki = 0; ki < NK; ki++) {
        cp_wait1();
        __syncthreads();

        if (wid < 8) {
            // ---- tensor-pipe slice: cols [0,104) ----
            const uint32_t sA = sbase + (uint32_t)(ki % STG) * STAGE_B;
            const uint32_t sB = sA + OP_BYTES;
#pragma unroll
            for (int ks = 0; ks < 4; ks++) {
                const int chunk = ks * 2 + kg;
                uint32_t a[4];
                {
                    int row = wid * 16 + r16;
                    ldsm4(a[0], a[1], a[2], a[3], sA + row * 128 + ((chunk ^ (row & 7)) << 4));
                }
                uint32_t b[7][4];
#pragma unroll
                for (int br = 0; br < 7; br++) {
                    int row = br * 16 + r16;
                    ldsm4(b[br][0], b[br][1], b[br][2], b[br][3],
                          sB + row * 128 + ((chunk ^ (row & 7)) << 4));
                }
#pragma unroll
                for (int t = 0; t < 13; t++)
                    mma16816(acc[t], a, b[t >> 1][t & 1], b[t >> 1][2 + (t & 1)]);
            }
        } else {
            // ---- fma-pipe slice: cols [104,128) ----
            const char* sA = smraw + (size_t)(ki % STG) * STAGE_B;
            const char* sB = sA + OP_BYTES;
#pragma unroll
            for (int kh = 0; kh < 2; kh++) {
#pragma unroll
                for (int kq = 0; kq < 16; kq++) {
                    const int k2 = kh * 16 + kq;          // k-pair index 0..31
                    const int chunk = k2 >> 2;
                    const int intra = (k2 & 3) * 4;
                    __half2 a2[4], b2[6];
#pragma unroll
                    for (int i = 0; i < 4; i++) {
                        int row = fm + i;
                        a2[i] = *reinterpret_cast<const __half2*>(
                            sA + row * 128 + ((chunk ^ (row & 7)) << 4) + intra);
                    }
#pragma unroll
                    for (int j = 0; j < 6; j++) {
                        int row = fn + j;
                        b2[j] = *reinterpret_cast<const __half2*>(
                            sB + row * 128 + ((chunk ^ (row & 7)) << 4) + intra);
                    }
#pragma unroll
                    for (int i = 0; i < 4; i++)
#pragma unroll
                        for (int j = 0; j < 6; j++)
                            acch[i][j] = __hfma2(a2[i], b2[j], acch[i][j]);
                }
                // promote fp16 partials to fp32 every 32 K elements
#pragma unroll
                for (int i = 0; i < 4; i++)
#pragma unroll
                    for (int j = 0; j < 6; j++) {
                        float2 f = __half22float2(acch[i][j]);
                        accf[i][j] += f.x + f.y;
                        acch[i][j] = __float2half2_rn(0.0f);
                    }
            }
        }

        if (ki + 2 < NK) load_stage(sbase + ((ki + 2) % STG) * STAGE_B, m0, n0, ki + 2, tid);
        cp_commit();
    }

    if (wid < 8) {
        // mma epilogue: warp w owns rows m0 + w*16 .. +16, cols [0,104)
        const int qr = lane >> 2, qc = lane & 3;
        int r0 = m0 + wid * 16 + qr;
#pragma unroll
        for (int t = 0; t < 13; t++) {
            int col = n0 + t * 8 + qc * 2;
            float2 bb = *reinterpret_cast<const float2*>(bias + col);
            float2 v0, v1;
            v0.x = acc[t][0] + bb.x;  v0.y = acc[t][1] + bb.y;
            v1.x = acc[t][2] + bb.x;  v1.y = acc[t][3] + bb.y;
            *reinterpret_cast<float2*>(out + (size_t)r0 * N_DIM + col) = v0;
            *reinterpret_cast<float2*>(out + (size_t)(r0 + 8) * N_DIM + col) = v1;
        }
    } else {
        // ffma epilogue: transpose through free stage-1 smem for coalesced stores
        float* sD = reinterpret_cast<float*>(smraw + STAGE_B);   // stage 1 unused after ki=63
#pragma unroll
        for (int i = 0; i < 4; i++)
#pragma unroll
            for (int j = 0; j < 6; j++)
                sD[(fm + i) * 28 + fnl + j] = accf[i][j];
        asm volatile("bar.sync 1, 128;" ::: "memory");
        int m = m0 + ft;
        const float* sDr = sD + ft * 28;
#pragma unroll
        for (int v = 0; v < 6; v++) {
            float4 d  = *reinterpret_cast<const float4*>(sDr + v * 4);
            float4 bb = *reinterpret_cast<const float4*>(bias + n0 + 104 + v * 4);
            d.x += bb.x; d.y += bb.y; d.z += bb.z; d.w += bb.w;
            *reinterpret_cast<float4*>(out + (size_t)m * N_DIM + n0 + 104 + v * 4) = d;
        }
    }
}

// ---------------- launch ----------------
extern "C" void kernel_launch(void* const* d_in, const int* in_sizes, int n_in,
                              void* d_out, int out_size) {
    (void)in_sizes; (void)n_in; (void)out_size;
    const float4* x4 = reinterpret_cast<const float4*>(d_in[0]);
    const float4* w4 = reinterpret_cast<const float4*>(d_in[1]);
    const float*  bias = reinterpret_cast<const float*>(d_in[2]);
    float* out = reinterpret_cast<float*>(d_out);

    const int NW4 = (N_DIM * K_DIM) / 4;

    cudaFuncSetAttribute(gemm_kernel, cudaFuncAttributeMaxDynamicSharedMemorySize, SMEM_GEMM);

    zero_kernel<<<512, 256>>>();
    hist1_kernel<<<1184, 256>>>(w4, NW4);
    scan1_kernel<<<1, 1024>>>(RANK_K);
    hist2_convx_kernel<<<XBLK + HBLK, 256>>>(x4, w4);
    scan2_kernel<<<1, 1024>>>(RANK_K);
    conv_w_kernel<<<592, 256>>>(w4, NW4);
    gemm_kernel<<<dim3(N_DIM / BN, M_DIM / BM), NTHR, SMEM_GEMM>>>(bias, out);
}

// round 16
// speedup vs baseline: 1.5745x; 1.5745x over previous
#include <cuda_runtime.h>
#include <cuda_fp16.h>
#include <cstdint>

#define M_DIM 8192
#define N_DIM 4096
#define K_DIM 4096
#define RANK_K 15099493u   // floor(0.9f * 16777215.0f) in fp32 semantics, frac == 0

// ---------------- device scratch (static globals: allowed) ----------------
// g_hist1/g_hist2 start zeroed (module load) and are re-zeroed by scan1/scan2
// after being consumed, so every kernel_launch call sees them zeroed (invariant).
__device__ __half   g_X16[(size_t)M_DIM * K_DIM];   // 64 MB
__device__ __half   g_W16[(size_t)N_DIM * K_DIM];   // 32 MB
__device__ unsigned g_hist1[8192];
__device__ unsigned g_hist2[262144];
__device__ unsigned g_selP;
__device__ unsigned g_selBase;
__device__ float    g_thresh;

// ---------------- PTX helpers (base ISA only) ----------------
__device__ __forceinline__ uint32_t smem_u32(const void* p) {
    uint32_t a;
    asm("{ .reg .u64 t; cvta.to.shared.u64 t, %1; cvt.u32.u64 %0, t; }" : "=r"(a) : "l"(p));
    return a;
}
__device__ __forceinline__ void cp16(uint32_t s, const void* g) {
    asm volatile("cp.async.cg.shared.global [%0], [%1], 16;" :: "r"(s), "l"(g));
}
__device__ __forceinline__ void cp_commit() { asm volatile("cp.async.commit_group;" ::: "memory"); }
__device__ __forceinline__ void cp_wait1()  { asm volatile("cp.async.wait_group 1;" ::: "memory"); }

__device__ __forceinline__ void ldsm4(uint32_t& r0, uint32_t& r1, uint32_t& r2, uint32_t& r3,
                                      uint32_t addr) {
    asm volatile("ldmatrix.sync.aligned.m8n8.x4.shared.b16 {%0,%1,%2,%3}, [%4];"
                 : "=r"(r0), "=r"(r1), "=r"(r2), "=r"(r3) : "r"(addr));
}

__device__ __forceinline__ void mma16816(float* c, const uint32_t* a, uint32_t b0, uint32_t b1) {
    asm volatile(
        "mma.sync.aligned.m16n8k16.row.col.f32.f16.f16.f32 "
        "{%0,%1,%2,%3}, {%4,%5,%6,%7}, {%8,%9}, {%0,%1,%2,%3};"
        : "+f"(c[0]), "+f"(c[1]), "+f"(c[2]), "+f"(c[3])
        : "r"(a[0]), "r"(a[1]), "r"(a[2]), "r"(a[3]), "r"(b0), "r"(b1));
}

// ---------------- selection: exact order statistic of |w| bits ----------------
__global__ void hist1_kernel(const float4* __restrict__ w, int n4) {
    __shared__ unsigned sh[8192];
    for (int i = threadIdx.x; i < 8192; i += blockDim.x) sh[i] = 0;
    __syncthreads();
    int idx = blockIdx.x * blockDim.x + threadIdx.x;
    int stride = gridDim.x * blockDim.x;
    for (int i = idx; i < n4; i += stride) {
        float4 v = w[i];
        atomicAdd(&sh[(__float_as_uint(v.x) & 0x7FFFFFFFu) >> 18], 1u);
        atomicAdd(&sh[(__float_as_uint(v.y) & 0x7FFFFFFFu) >> 18], 1u);
        atomicAdd(&sh[(__float_as_uint(v.z) & 0x7FFFFFFFu) >> 18], 1u);
        atomicAdd(&sh[(__float_as_uint(v.w) & 0x7FFFFFFFu) >> 18], 1u);
    }
    __syncthreads();
    for (int i = threadIdx.x; i < 8192; i += blockDim.x) {
        unsigned c = sh[i];
        if (c) atomicAdd(&g_hist1[i], c);
    }
}

// scan1: consumes g_hist1 and RE-ZEROES it (self-cleaning; keeps cross-call invariant)
__global__ void scan1_kernel(unsigned rank) {
    __shared__ unsigned partial[1024];
    int t = threadIdx.x;
    unsigned v[8];
    unsigned s = 0;
#pragma unroll
    for (int i = 0; i < 8; i++) { v[i] = g_hist1[t * 8 + i]; s += v[i]; }
#pragma unroll
    for (int i = 0; i < 8; i++) g_hist1[t * 8 + i] = 0u;
    partial[t] = s;
    __syncthreads();
    for (int ofs = 1; ofs < 1024; ofs <<= 1) {
        unsigned x = (t >= ofs) ? partial[t - ofs] : 0u;
        __syncthreads();
        partial[t] += x;
        __syncthreads();
    }
    unsigned base = partial[t] - s;  // exclusive prefix
    if (rank >= base && rank < partial[t]) {
        unsigned cum = base;
#pragma unroll
        for (int i = 0; i < 8; i++) {
            if (rank < cum + v[i]) { g_selP = (unsigned)(t * 8 + i); g_selBase = cum; break; }
            cum += v[i];
        }
    }
}

// hist2 (W) fused with conv_x (X) -- independent workloads, concurrent DRAM streams
#define XBLK 1184
#define HBLK 592
__global__ void hist2_convx_kernel(const float4* __restrict__ x, const float4* __restrict__ w) {
    if (blockIdx.x < XBLK) {
        int idx = blockIdx.x * blockDim.x + threadIdx.x;
        int stride = XBLK * blockDim.x;
        uint2* out = reinterpret_cast<uint2*>(g_X16);
        const int n4 = (M_DIM * K_DIM) / 4;
        for (int i = idx; i < n4; i += stride) {
            float4 v = x[i];
            __half2 h0 = __floats2half2_rn(v.x, v.y);
            __half2 h1 = __floats2half2_rn(v.z, v.w);
            uint2 o;
            o.x = *reinterpret_cast<unsigned*>(&h0);
            o.y = *reinterpret_cast<unsigned*>(&h1);
            out[i] = o;
        }
    } else {
        unsigned P = g_selP;
        int idx = (blockIdx.x - XBLK) * blockDim.x + threadIdx.x;
        int stride = HBLK * blockDim.x;
        const int n4 = (N_DIM * K_DIM) / 4;
        for (int i = idx; i < n4; i += stride) {
            float4 v = w[i];
            unsigned b;
            b = __float_as_uint(v.x) & 0x7FFFFFFFu; if ((b >> 18) == P) atomicAdd(&g_hist2[b & 0x3FFFFu], 1u);
            b = __float_as_uint(v.y) & 0x7FFFFFFFu; if ((b >> 18) == P) atomicAdd(&g_hist2[b & 0x3FFFFu], 1u);
            b = __float_as_uint(v.z) & 0x7FFFFFFFu; if ((b >> 18) == P) atomicAdd(&g_hist2[b & 0x3FFFFu], 1u);
            b = __float_as_uint(v.w) & 0x7FFFFFFFu; if ((b >> 18) == P) atomicAdd(&g_hist2[b & 0x3FFFFu], 1u);
        }
    }
}

// scan2: consumes g_hist2 and RE-ZEROES it (self-cleaning)
__global__ void scan2_kernel(unsigned rank) {
    __shared__ unsigned partial[1024];
    int t = threadIdx.x;
    unsigned loc[256];
    unsigned s = 0;
    for (int i = 0; i < 256; i++) { loc[i] = g_hist2[t * 256 + i]; s += loc[i]; }
    for (int i = 0; i < 256; i++) g_hist2[t * 256 + i] = 0u;
    partial[t] = s;
    __syncthreads();
    for (int ofs = 1; ofs < 1024; ofs <<= 1) {
        unsigned x = (t >= ofs) ? partial[t - ofs] : 0u;
        __syncthreads();
        partial[t] += x;
        __syncthreads();
    }
    unsigned base = partial[t] - s;
    unsigned rl = rank - g_selBase;
    if (rl >= base && rl < partial[t]) {
        unsigned cum = base;
        for (int i = 0; i < 256; i++) {
            unsigned c = loc[i];
            if (rl < cum + c) {
                g_thresh = __uint_as_float((g_selP << 18) | (unsigned)(t * 256 + i));
                break;
            }
            cum += c;
        }
    }
}

__global__ void conv_w_kernel(const float4* __restrict__ w, int n4) {
    float t = g_thresh;
    int idx = blockIdx.x * blockDim.x + threadIdx.x;
    int stride = gridDim.x * blockDim.x;
    uint2* out = reinterpret_cast<uint2*>(g_W16);
    for (int i = idx; i < n4; i += stride) {
        float4 v = w[i];
        float a0 = (fabsf(v.x) >= t) ? v.x : 0.0f;
        float a1 = (fabsf(v.y) >= t) ? v.y : 0.0f;
        float a2 = (fabsf(v.z) >= t) ? v.z : 0.0f;
        float a3 = (fabsf(v.w) >= t) ? v.w : 0.0f;
        __half2 h0 = __floats2half2_rn(a0, a1);
        __half2 h1 = __floats2half2_rn(a2, a3);
        uint2 o;
        o.x = *reinterpret_cast<unsigned*>(&h0);
        o.y = *reinterpret_cast<unsigned*>(&h1);
        out[i] = o;
    }
}

// ---- GEMM: 128x128 CTA tile, 4 warps (64x64 warp tiles), 3-stage cp.async, occ=2,
// ----       single __syncthreads per K-iteration (wait -> sync -> compute -> load-next)
#define BM 128
#define BN 128
#define BKH 64                      // K halves per stage (128 B rows -> SW128)
#define NK (K_DIM / BKH)            // 64
#define STG 3
#define OP_BYTES (BM * 128)         // 16384
#define STAGE_B (2 * OP_BYTES)      // 32768
#define SMEM_GEMM (STG * STAGE_B)   // 98304 per CTA (x2 CTAs = 192K < 228K)
#define NTHR 128

__device__ __forceinline__ void load_stage(uint32_t st, int m0, int n0, int kidx, int tid) {
    const __half* Xp = g_X16 + (size_t)m0 * K_DIM + (size_t)kidx * BKH;
    const __half* Wp = g_W16 + (size_t)n0 * K_DIM + (size_t)kidx * BKH;
#pragma unroll
    for (int i = 0; i < 8; i++) {
        int c = tid + i * NTHR;          // 0..1023 (128 rows x 8 chunks)
        int row = c >> 3, ci = c & 7;
        cp16(st + row * 128 + ((ci ^ (row & 7)) << 4), Xp + (size_t)row * K_DIM + ci * 8);
    }
#pragma unroll
    for (int i = 0; i < 8; i++) {
        int c = tid + i * NTHR;
        int row = c >> 3, ci = c & 7;
        cp16(st + OP_BYTES + row * 128 + ((ci ^ (row & 7)) << 4), Wp + (size_t)row * K_DIM + ci * 8);
    }
}

__global__ void __launch_bounds__(NTHR, 2) gemm_kernel(const float* __restrict__ bias,
                                                       float* __restrict__ out) {
    extern __shared__ char smraw[];
    const uint32_t sbase = smem_u32(smraw);
    const int tid = threadIdx.x;
    const int wid = tid >> 5;
    const int lane = tid & 31;
    const int warp_m = wid >> 1;     // 0..1 (64 rows each)
    const int warp_n = wid & 1;      // 0..1 (64 cols each)
    const int m0 = blockIdx.y * BM;
    const int n0 = blockIdx.x * BN;

    float acc[4][8][4];
#pragma unroll
    for (int i = 0; i < 4; i++)
#pragma unroll
        for (int j = 0; j < 8; j++)
#pragma unroll
            for (int k = 0; k < 4; k++) acc[i][j][k] = 0.0f;

    // ldmatrix lane geometry
    const int g  = lane >> 3;             // 0..3
    const int lr = lane & 7;
    const int r16 = ((g & 1) << 3) + lr;  // row within a 16-row tile
    const int kg  = g >> 1;               // 16B chunk parity within k16

    // prologue: stages 0,1 in flight
    load_stage(sbase + 0 * STAGE_B, m0, n0, 0, tid); cp_commit();
    load_stage(sbase + 1 * STAGE_B, m0, n0, 1, tid); cp_commit();

    for (int ki = 0; ki < NK; ki++) {
        cp_wait1();          // own groups: stage ki arrived (<=1 group outstanding)
        __syncthreads();     // all warps' portions visible; also closes iter ki-1 reads

        const uint32_t sA = sbase + (uint32_t)(ki % STG) * STAGE_B;
        const uint32_t sB = sA + OP_BYTES;

#pragma unroll
        for (int ks = 0; ks < 4; ks++) {            // 4 x k16 per stage
            const int chunk = ks * 2 + kg;           // 16B chunk index 0..7
            uint32_t a[4][4], b[4][4];
#pragma unroll
            for (int mt = 0; mt < 4; mt++) {
                int row = warp_m * 64 + mt * 16 + r16;
                uint32_t ad = sA + row * 128 + ((chunk ^ (row & 7)) << 4);
                ldsm4(a[mt][0], a[mt][1], a[mt][2], a[mt][3], ad);
            }
#pragma unroll
            for (int bt = 0; bt < 4; bt++) {
                int row = warp_n * 64 + bt * 16 + r16;
                uint32_t ad = sB + row * 128 + ((chunk ^ (row & 7)) << 4);
                ldsm4(b[bt][0], b[bt][1], b[bt][2], b[bt][3], ad);
            }
#pragma unroll
            for (int mt = 0; mt < 4; mt++)
#pragma unroll
                for (int nt = 0; nt < 8; nt++) {
                    int bt = nt >> 1, od = nt & 1;
                    mma16816(acc[mt][nt], a[mt], b[bt][od], b[bt][2 + od]);
                }
        }

        // load stage ki+2 AFTER compute: its buffer (ki+2)%3 == (ki-1)%3, whose readers
        // (iteration ki-1) are provably done once any warp passed this iteration's sync.
        if (ki + 2 < NK) load_stage(sbase + ((ki + 2) % STG) * STAGE_B, m0, n0, ki + 2, tid);
        cp_commit();
    }

    // epilogue
    const int qr = lane >> 2, qc = lane & 3;
#pragma unroll
    for (int nt = 0; nt < 8; nt++) {
        int col = n0 + warp_n * 64 + nt * 8 + qc * 2;
        float2 bb = *reinterpret_cast<const float2*>(bias + col);
#pragma unroll
        for (int mt = 0; mt < 4; mt++) {
            int r0 = m0 + warp_m * 64 + mt * 16 + qr;
            float2 v0, v1;
            v0.x = acc[mt][nt][0] + bb.x;  v0.y = acc[mt][nt][1] + bb.y;
            v1.x = acc[mt][nt][2] + bb.x;  v1.y = acc[mt][nt][3] + bb.y;
            *reinterpret_cast<float2*>(out + (size_t)r0 * N_DIM + col) = v0;
            *reinterpret_cast<float2*>(out + (size_t)(r0 + 8) * N_DIM + col) = v1;
        }
    }
}

// ---------------- launch ----------------
extern "C" void kernel_launch(void* const* d_in, const int* in_sizes, int n_in,
                              void* d_out, int out_size) {
    (void)in_sizes; (void)n_in; (void)out_size;
    const float4* x4 = reinterpret_cast<const float4*>(d_in[0]);
    const float4* w4 = reinterpret_cast<const float4*>(d_in[1]);
    const float*  bias = reinterpret_cast<const float*>(d_in[2]);
    float* out = reinterpret_cast<float*>(d_out);

    const int NW4 = (N_DIM * K_DIM) / 4;

    cudaFuncSetAttribute(gemm_kernel, cudaFuncAttributeMaxDynamicSharedMemorySize, SMEM_GEMM);

    hist1_kernel<<<1184, 256>>>(w4, NW4);
    scan1_kernel<<<1, 1024>>>(RANK_K);
    hist2_convx_kernel<<<XBLK + HBLK, 256>>>(x4, w4);
    scan2_kernel<<<1, 1024>>>(RANK_K);
    conv_w_kernel<<<1184, 256>>>(w4, NW4);
    gemm_kernel<<<dim3(N_DIM / BN, M_DIM / BM), NTHR, SMEM_GEMM>>>(bias, out);
}

// round 17
// speedup vs baseline: 2.4166x; 1.5348x over previous
#include <cuda_runtime.h>
#include <cuda_fp16.h>
#include <cstdint>

#define M_DIM 8192
#define N_DIM 4096
#define K_DIM 4096
#define RANK_K 15099493u   // floor(0.9f * 16777215.0f) in fp32 semantics, frac == 0

// ---------------- device scratch (static globals: allowed) ----------------
// g_hist1/g_hist2 start zeroed (module load) and are re-zeroed by scan1/scan2
// after being consumed, so every kernel_launch call sees them zeroed (invariant).
__device__ __half   g_X16[(size_t)M_DIM * K_DIM];   // 64 MB
__device__ __half   g_W16[(size_t)N_DIM * K_DIM];   // 32 MB
__device__ unsigned g_hist1[8192];
__device__ unsigned g_hist2[262144];
__device__ unsigned g_selP;
__device__ unsigned g_selBase;
__device__ float    g_thresh;

// ---------------- PTX helpers (base ISA only) ----------------
__device__ __forceinline__ uint32_t smem_u32(const void* p) {
    uint32_t a;
    asm("{ .reg .u64 t; cvta.to.shared.u64 t, %1; cvt.u32.u64 %0, t; }" : "=r"(a) : "l"(p));
    return a;
}
__device__ __forceinline__ void cp16(uint32_t s, const void* g) {
    asm volatile("cp.async.cg.shared.global [%0], [%1], 16;" :: "r"(s), "l"(g));
}
__device__ __forceinline__ void cp_commit() { asm volatile("cp.async.commit_group;" ::: "memory"); }
__device__ __forceinline__ void cp_wait1()  { asm volatile("cp.async.wait_group 1;" ::: "memory"); }

__device__ __forceinline__ void ldsm4(uint32_t& r0, uint32_t& r1, uint32_t& r2, uint32_t& r3,
                                      uint32_t addr) {
    asm volatile("ldmatrix.sync.aligned.m8n8.x4.shared.b16 {%0,%1,%2,%3}, [%4];"
                 : "=r"(r0), "=r"(r1), "=r"(r2), "=r"(r3) : "r"(addr));
}

__device__ __forceinline__ void mma16816(float* c, const uint32_t* a, uint32_t b0, uint32_t b1) {
    asm volatile(
        "mma.sync.aligned.m16n8k16.row.col.f32.f16.f16.f32 "
        "{%0,%1,%2,%3}, {%4,%5,%6,%7}, {%8,%9}, {%0,%1,%2,%3};"
        : "+f"(c[0]), "+f"(c[1]), "+f"(c[2]), "+f"(c[3])
        : "r"(a[0]), "r"(a[1]), "r"(a[2]), "r"(a[3]), "r"(b0), "r"(b1));
}

// ---------------- selection: exact order statistic of |w| bits ----------------
__global__ void hist1_kernel(const float4* __restrict__ w, int n4) {
    __shared__ unsigned sh[8192];
    for (int i = threadIdx.x; i < 8192; i += blockDim.x) sh[i] = 0;
    __syncthreads();
    int idx = blockIdx.x * blockDim.x + threadIdx.x;
    int stride = gridDim.x * blockDim.x;
    for (int i = idx; i < n4; i += stride) {
        float4 v = w[i];
        atomicAdd(&sh[(__float_as_uint(v.x) & 0x7FFFFFFFu) >> 18], 1u);
        atomicAdd(&sh[(__float_as_uint(v.y) & 0x7FFFFFFFu) >> 18], 1u);
        atomicAdd(&sh[(__float_as_uint(v.z) & 0x7FFFFFFFu) >> 18], 1u);
        atomicAdd(&sh[(__float_as_uint(v.w) & 0x7FFFFFFFu) >> 18], 1u);
    }
    __syncthreads();
    for (int i = threadIdx.x; i < 8192; i += blockDim.x) {
        unsigned c = sh[i];
        if (c) atomicAdd(&g_hist1[i], c);
    }
}

// scan1: consumes g_hist1 and RE-ZEROES it (8 regs/thread -- no spill)
__global__ void scan1_kernel(unsigned rank) {
    __shared__ unsigned partial[1024];
    int t = threadIdx.x;
    unsigned v[8];
    unsigned s = 0;
#pragma unroll
    for (int i = 0; i < 8; i++) { v[i] = g_hist1[t * 8 + i]; s += v[i]; }
#pragma unroll
    for (int i = 0; i < 8; i++) g_hist1[t * 8 + i] = 0u;
    partial[t] = s;
    __syncthreads();
    for (int ofs = 1; ofs < 1024; ofs <<= 1) {
        unsigned x = (t >= ofs) ? partial[t - ofs] : 0u;
        __syncthreads();
        partial[t] += x;
        __syncthreads();
    }
    unsigned base = partial[t] - s;  // exclusive prefix
    if (rank >= base && rank < partial[t]) {
        unsigned cum = base;
#pragma unroll
        for (int i = 0; i < 8; i++) {
            if (rank < cum + v[i]) { g_selP = (unsigned)(t * 8 + i); g_selBase = cum; break; }
            cum += v[i];
        }
    }
}

// hist2 (W) fused with conv_x (X) -- independent workloads, concurrent DRAM streams
#define XBLK 1184
#define HBLK 592
__global__ void hist2_convx_kernel(const float4* __restrict__ x, const float4* __restrict__ w) {
    if (blockIdx.x < XBLK) {
        int idx = blockIdx.x * blockDim.x + threadIdx.x;
        int stride = XBLK * blockDim.x;
        uint2* out = reinterpret_cast<uint2*>(g_X16);
        const int n4 = (M_DIM * K_DIM) / 4;
        for (int i = idx; i < n4; i += stride) {
            float4 v = x[i];
            __half2 h0 = __floats2half2_rn(v.x, v.y);
            __half2 h1 = __floats2half2_rn(v.z, v.w);
            uint2 o;
            o.x = *reinterpret_cast<unsigned*>(&h0);
            o.y = *reinterpret_cast<unsigned*>(&h1);
            out[i] = o;
        }
    } else {
        unsigned P = g_selP;
        int idx = (blockIdx.x - XBLK) * blockDim.x + threadIdx.x;
        int stride = HBLK * blockDim.x;
        const int n4 = (N_DIM * K_DIM) / 4;
        for (int i = idx; i < n4; i += stride) {
            float4 v = w[i];
            unsigned b;
            b = __float_as_uint(v.x) & 0x7FFFFFFFu; if ((b >> 18) == P) atomicAdd(&g_hist2[b & 0x3FFFFu], 1u);
            b = __float_as_uint(v.y) & 0x7FFFFFFFu; if ((b >> 18) == P) atomicAdd(&g_hist2[b & 0x3FFFFu], 1u);
            b = __float_as_uint(v.z) & 0x7FFFFFFFu; if ((b >> 18) == P) atomicAdd(&g_hist2[b & 0x3FFFFu], 1u);
            b = __float_as_uint(v.w) & 0x7FFFFFFFu; if ((b >> 18) == P) atomicAdd(&g_hist2[b & 0x3FFFFu], 1u);
        }
    }
}

// scan2: two passes over gmem (NO per-thread 256-array -- that spilled in R16),
// then re-zeroes own bins AFTER the find phase (barrier-ordered).
__global__ void scan2_kernel(unsigned rank) {
    __shared__ unsigned partial[1024];
    int t = threadIdx.x;
    unsigned s = 0;
    for (int i = 0; i < 256; i++) s += g_hist2[t * 256 + i];
    partial[t] = s;
    __syncthreads();
    for (int ofs = 1; ofs < 1024; ofs <<= 1) {
        unsigned x = (t >= ofs) ? partial[t - ofs] : 0u;
        __syncthreads();
        partial[t] += x;
        __syncthreads();
    }
    unsigned base = partial[t] - s;
    unsigned rl = rank - g_selBase;
    if (rl >= base && rl < partial[t]) {
        unsigned cum = base;
        for (int i = 0; i < 256; i++) {
            unsigned c = g_hist2[t * 256 + i];
            if (rl < cum + c) {
                g_thresh = __uint_as_float((g_selP << 18) | (unsigned)(t * 256 + i));
                break;
            }
            cum += c;
        }
    }
    __syncthreads();   // find-phase reads complete before anyone zeroes
    for (int i = 0; i < 256; i++) g_hist2[t * 256 + i] = 0u;
}

__global__ void conv_w_kernel(const float4* __restrict__ w, int n4) {
    float t = g_thresh;
    int idx = blockIdx.x * blockDim.x + threadIdx.x;
    int stride = gridDim.x * blockDim.x;
    uint2* out = reinterpret_cast<uint2*>(g_W16);
    for (int i = idx; i < n4; i += stride) {
        float4 v = w[i];
        float a0 = (fabsf(v.x) >= t) ? v.x : 0.0f;
        float a1 = (fabsf(v.y) >= t) ? v.y : 0.0f;
        float a2 = (fabsf(v.z) >= t) ? v.z : 0.0f;
        float a3 = (fabsf(v.w) >= t) ? v.w : 0.0f;
        __half2 h0 = __floats2half2_rn(a0, a1);
        __half2 h1 = __floats2half2_rn(a2, a3);
        uint2 o;
        o.x = *reinterpret_cast<unsigned*>(&h0);
        o.y = *reinterpret_cast<unsigned*>(&h1);
        out[i] = o;
    }
}

// ---- GEMM: 128x128 CTA tile, 4 warps (64x64 warp tiles), 3-stage cp.async, occ=2,
// ----       single __syncthreads per K-iteration (wait -> sync -> compute -> load-next)
#define BM 128
#define BN 128
#define BKH 64                      // K halves per stage (128 B rows -> SW128)
#define NK (K_DIM / BKH)            // 64
#define STG 3
#define OP_BYTES (BM * 128)         // 16384
#define STAGE_B (2 * OP_BYTES)      // 32768
#define SMEM_GEMM (STG * STAGE_B)   // 98304 per CTA (x2 CTAs = 192K < 228K)
#define NTHR 128

__device__ __forceinline__ void load_stage(uint32_t st, int m0, int n0, int kidx, int tid) {
    const __half* Xp = g_X16 + (size_t)m0 * K_DIM + (size_t)kidx * BKH;
    const __half* Wp = g_W16 + (size_t)n0 * K_DIM + (size_t)kidx * BKH;
#pragma unroll
    for (int i = 0; i < 8; i++) {
        int c = tid + i * NTHR;          // 0..1023 (128 rows x 8 chunks)
        int row = c >> 3, ci = c & 7;
        cp16(st + row * 128 + ((ci ^ (row & 7)) << 4), Xp + (size_t)row * K_DIM + ci * 8);
    }
#pragma unroll
    for (int i = 0; i < 8; i++) {
        int c = tid + i * NTHR;
        int row = c >> 3, ci = c & 7;
        cp16(st + OP_BYTES + row * 128 + ((ci ^ (row & 7)) << 4), Wp + (size_t)row * K_DIM + ci * 8);
    }
}

__global__ void __launch_bounds__(NTHR, 2) gemm_kernel(const float* __restrict__ bias,
                                                       float* __restrict__ out) {
    extern __shared__ char smraw[];
    const uint32_t sbase = smem_u32(smraw);
    const int tid = threadIdx.x;
    const int wid = tid >> 5;
    const int lane = tid & 31;
    const int warp_m = wid >> 1;     // 0..1 (64 rows each)
    const int warp_n = wid & 1;      // 0..1 (64 cols each)
    const int m0 = blockIdx.y * BM;
    const int n0 = blockIdx.x * BN;

    float acc[4][8][4];
#pragma unroll
    for (int i = 0; i < 4; i++)
#pragma unroll
        for (int j = 0; j < 8; j++)
#pragma unroll
            for (int k = 0; k < 4; k++) acc[i][j][k] = 0.0f;

    // ldmatrix lane geometry
    const int g  = lane >> 3;             // 0..3
    const int lr = lane & 7;
    const int r16 = ((g & 1) << 3) + lr;  // row within a 16-row tile
    const int kg  = g >> 1;               // 16B chunk parity within k16

    // prologue: stages 0,1 in flight
    load_stage(sbase + 0 * STAGE_B, m0, n0, 0, tid); cp_commit();
    load_stage(sbase + 1 * STAGE_B, m0, n0, 1, tid); cp_commit();

    for (int ki = 0; ki < NK; ki++) {
        cp_wait1();          // own groups: stage ki arrived (<=1 group outstanding)
        __syncthreads();     // all warps' portions visible; also closes iter ki-1 reads

        const uint32_t sA = sbase + (uint32_t)(ki % STG) * STAGE_B;
        const uint32_t sB = sA + OP_BYTES;

#pragma unroll
        for (int ks = 0; ks < 4; ks++) {            // 4 x k16 per stage
            const int chunk = ks * 2 + kg;           // 16B chunk index 0..7
            uint32_t a[4][4], b[4][4];
#pragma unroll
            for (int mt = 0; mt < 4; mt++) {
                int row = warp_m * 64 + mt * 16 + r16;
                uint32_t ad = sA + row * 128 + ((chunk ^ (row & 7)) << 4);
                ldsm4(a[mt][0], a[mt][1], a[mt][2], a[mt][3], ad);
            }
#pragma unroll
            for (int bt = 0; bt < 4; bt++) {
                int row = warp_n * 64 + bt * 16 + r16;
                uint32_t ad = sB + row * 128 + ((chunk ^ (row & 7)) << 4);
                ldsm4(b[bt][0], b[bt][1], b[bt][2], b[bt][3], ad);
            }
#pragma unroll
            for (int mt = 0; mt < 4; mt++)
#pragma unroll
                for (int nt = 0; nt < 8; nt++) {
                    int bt = nt >> 1, od = nt & 1;
                    mma16816(acc[mt][nt], a[mt], b[bt][od], b[bt][2 + od]);
                }
        }

        // load stage ki+2 AFTER compute: its buffer (ki+2)%3 == (ki-1)%3, whose readers
        // (iteration ki-1) are provably done once any warp passed this iteration's sync.
        if (ki + 2 < NK) load_stage(sbase + ((ki + 2) % STG) * STAGE_B, m0, n0, ki + 2, tid);
        cp_commit();
    }

    // epilogue
    const int qr = lane >> 2, qc = lane & 3;
#pragma unroll
    for (int nt = 0; nt < 8; nt++) {
        int col = n0 + warp_n * 64 + nt * 8 + qc * 2;
        float2 bb = *reinterpret_cast<const float2*>(bias + col);
#pragma unroll
        for (int mt = 0; mt < 4; mt++) {
            int r0 = m0 + warp_m * 64 + mt * 16 + qr;
            float2 v0, v1;
            v0.x = acc[mt][nt][0] + bb.x;  v0.y = acc[mt][nt][1] + bb.y;
            v1.x = acc[mt][nt][2] + bb.x;  v1.y = acc[mt][nt][3] + bb.y;
            *reinterpret_cast<float2*>(out + (size_t)r0 * N_DIM + col) = v0;
            *reinterpret_cast<float2*>(out + (size_t)(r0 + 8) * N_DIM + col) = v1;
        }
    }
}

// ---------------- launch ----------------
extern "C" void kernel_launch(void* const* d_in, const int* in_sizes, int n_in,
                              void* d_out, int out_size) {
    (void)in_sizes; (void)n_in; (void)out_size;
    const float4* x4 = reinterpret_cast<const float4*>(d_in[0]);
    const float4* w4 = reinterpret_cast<const float4*>(d_in[1]);
    const float*  bias = reinterpret_cast<const float*>(d_in[2]);
    float* out = reinterpret_cast<float*>(d_out);

    const int NW4 = (N_DIM * K_DIM) / 4;

    cudaFuncSetAttribute(gemm_kernel, cudaFuncAttributeMaxDynamicSharedMemorySize, SMEM_GEMM);

    hist1_kernel<<<1184, 256>>>(w4, NW4);
    scan1_kernel<<<1, 1024>>>(RANK_K);
    hist2_convx_kernel<<<XBLK + HBLK, 256>>>(x4, w4);
    scan2_kernel<<<1, 1024>>>(RANK_K);
    conv_w_kernel<<<1184, 256>>>(w4, NW4);
    gemm_kernel<<<dim3(N_DIM / BN, M_DIM / BM), NTHR, SMEM_GEMM>>>(bias, out);
}